// round 2
// baseline (speedup 1.0000x reference)
#include <cuda_runtime.h>
#include <cstdint>

// ---------------- configuration ----------------
#define TSTRIDE     1024        // padded tile stride in hist matrices (supports num_tile up to 32)
#define MAX_ROWS    8192        // supports N up to 4M at 512 pts/row
#define MAX_CHUNKS  256
#define PPW         512         // points per warp (one hist "row")
#define WPB         8           // warps per block
#define PPB         (PPW*WPB)   // 4096 points per block
#define CHUNK       64          // rows per scan chunk

// ---------------- static scratch (no runtime allocation) ----------------
__device__ int g_hist[MAX_ROWS * TSTRIDE];     // per-row tile histograms -> exclusive prefixes
__device__ int g_chunk[MAX_CHUNKS * TSTRIDE];  // per-chunk totals -> exclusive prefixes
__device__ int g_offsets[TSTRIDE];             // global tile offsets

// ---------------- helpers ----------------
__device__ __forceinline__ int tile_of(float v, float ts, int nt) {
    int t = (int)floorf(v / ts);
    t = t < 0 ? 0 : t;
    t = t > nt - 1 ? nt - 1 : t;
    return t;
}

// ---------------- pass 1: per-warp-row histogram ----------------
__global__ void k_hist(const float2* __restrict__ pos, const int* __restrict__ p_nt,
                       int N, int ROWS) {
    __shared__ int sh[WPB * TSTRIDE];   // 32 KB
    const int nt  = *p_nt;
    const int nt2 = nt * nt;
    const float ts = 1024.0f / (float)nt;

    const int w    = threadIdx.x >> 5;
    const int lane = threadIdx.x & 31;
    const int row  = blockIdx.x * WPB + w;

    // zero only this warp's columns
    for (int t = lane; t < nt2; t += 32) sh[w * TSTRIDE + t] = 0;
    __syncwarp();

    if (row >= ROWS) return;

    const int base = row * PPW;
#pragma unroll 4
    for (int i = 0; i < PPW / 32; i++) {
        int idx = base + i * 32 + lane;
        if (idx < N) {
            float2 p = pos[idx];
            int tx = tile_of(p.x, ts, nt);
            int ty = tile_of(p.y, ts, nt);
            atomicAdd(&sh[w * TSTRIDE + ty * nt + tx], 1);
        }
    }
    __syncwarp();
    for (int t = lane; t < nt2; t += 32)
        g_hist[(size_t)row * TSTRIDE + t] = sh[w * TSTRIDE + t];
}

// ---------------- pass 2a: per-tile scan over rows within each chunk ----------------
__global__ void k_scan_rows(const int* __restrict__ p_nt, int ROWS) {
    const int nt  = *p_nt;
    const int nt2 = nt * nt;
    const int c  = blockIdx.x;
    const int r0 = c * CHUNK;
    const int r1 = min(r0 + CHUNK, ROWS);

    for (int t = threadIdx.x; t < nt2; t += blockDim.x) {
        int run = 0;
        for (int r = r0; r < r1; r++) {
            int v = g_hist[(size_t)r * TSTRIDE + t];
            g_hist[(size_t)r * TSTRIDE + t] = run;
            run += v;
        }
        g_chunk[(size_t)c * TSTRIDE + t] = run;
    }
}

// ---------------- pass 2b: scan chunks per tile, then scan over tiles ----------------
__global__ void k_scan_tiles(const int* __restrict__ p_nt, int NCHUNKS,
                             float* __restrict__ out, int N) {
    __shared__ int s[1024];
    const int nt  = *p_nt;
    const int nt2 = nt * nt;
    const int t = threadIdx.x;

    int total = 0;
    if (t < nt2) {
        int run = 0;
        for (int c = 0; c < NCHUNKS; c++) {
            int v = g_chunk[(size_t)c * TSTRIDE + t];
            g_chunk[(size_t)c * TSTRIDE + t] = run;
            run += v;
        }
        total = run;
    }
    s[t] = total;
    __syncthreads();

    // Kogge-Stone inclusive scan over 1024 slots
    for (int off = 1; off < 1024; off <<= 1) {
        int v = (t >= off) ? s[t - off] : 0;
        __syncthreads();
        s[t] += v;
        __syncthreads();
    }
    int excl = s[t] - total;   // exclusive prefix

    if (t < nt2) {
        g_offsets[t] = excl;
        size_t feat_sz = (size_t)7 * (size_t)N;
        out[feat_sz + t]        = (float)total;  // tile_counts
        out[feat_sz + nt2 + t]  = (float)excl;   // tile_offsets
    }
}

// ---------------- pass 3: compute feat, stable rank, scatter ----------------
__global__ void k_scatter(const float2* __restrict__ pos,
                          const float4* __restrict__ cov,
                          const float*  __restrict__ opac,
                          const int*    __restrict__ p_nt,
                          int N, int ROWS,
                          float* __restrict__ out) {
    __shared__ int sb[WPB * TSTRIDE];   // 32 KB, per-warp base counters
    const int nt  = *p_nt;
    const int nt2 = nt * nt;
    const float ts = 1024.0f / (float)nt;

    const int w    = threadIdx.x >> 5;
    const int lane = threadIdx.x & 31;
    const int row  = blockIdx.x * WPB + w;

    float* __restrict__ out_feat  = out;
    float* __restrict__ out_order = out + (size_t)7 * (size_t)N + 2 * (size_t)nt2;

    if (row >= ROWS) return;

    // preload per-warp base: global tile offset + chunk prefix + row prefix
    const int chunk = row / CHUNK;
    for (int t = lane; t < nt2; t += 32)
        sb[w * TSTRIDE + t] = g_offsets[t]
                            + g_chunk[(size_t)chunk * TSTRIDE + t]
                            + g_hist[(size_t)row * TSTRIDE + t];
    __syncwarp();

    const int base = row * PPW;
    const unsigned lt_mask = (1u << lane) - 1u;

    for (int i = 0; i < PPW / 32; i++) {
        int idx = base + i * 32 + lane;
        bool valid = idx < N;

        float2 p = make_float2(0.f, 0.f);
        float ca = 0.f, cb = 0.f, cc = 0.f, rad = 0.f, op = 0.f;
        int key = 0x7FFFFFFF;   // sentinel for invalid lanes (never collides with a tile id)

        if (valid) {
            p = pos[idx];
            float4 cv = cov[idx];
            op = opac[idx];
            float a = cv.x, b = cv.y, c = cv.z, d = cv.w;
            float tr  = a + d;
            float det = a * d - b * c;
            float t1  = 0.5f * tr;
            float t2  = 0.5f * sqrtf(fmaxf(tr * tr - 4.0f * det, 0.0f));
            rad = fmaxf(t1 - t2, t1 + t2);
            float inv_det = 1.0f / det;
            ca =  d * inv_det;
            cb = -b * inv_det;
            cc =  a * inv_det;
            int tx = tile_of(p.x, ts, nt);
            int ty = tile_of(p.y, ts, nt);
            key = ty * nt + tx;
        }

        // stable rank within warp: groups of equal key in lane order
        unsigned m  = __match_any_sync(0xFFFFFFFFu, key);
        int leader  = __ffs(m) - 1;
        int cnt     = __popc(m);
        int rank_lt = __popc(m & lt_mask);

        int b0 = 0;
        if (lane == leader && valid) {
            b0 = sb[w * TSTRIDE + key];          // single writer per address: no atomic needed
            sb[w * TSTRIDE + key] = b0 + cnt;
        }
        b0 = __shfl_sync(0xFFFFFFFFu, b0, leader);

        if (valid) {
            size_t r = (size_t)(b0 + rank_lt);
            float* f = out_feat + r * 7;
            f[0] = p.x; f[1] = p.y;
            f[2] = ca;  f[3] = cb; f[4] = cc;
            f[5] = op;  f[6] = rad;
            out_order[r] = (float)idx;
        }
    }
}

// ---------------- launch ----------------
extern "C" void kernel_launch(void* const* d_in, const int* in_sizes, int n_in,
                              void* d_out, int out_size) {
    const float2* pos  = (const float2*)d_in[0];
    const float4* cov  = (const float4*)d_in[1];
    const float*  opac = (const float*) d_in[2];
    const int*    p_nt = (const int*)   d_in[3];
    float* out = (float*)d_out;

    const int N       = in_sizes[0] / 2;
    const int ROWS    = (N + PPW - 1) / PPW;
    const int NBLOCKS = (ROWS + WPB - 1) / WPB;
    const int NCHUNKS = (ROWS + CHUNK - 1) / CHUNK;

    k_hist      <<<NBLOCKS, 256>>>(pos, p_nt, N, ROWS);
    k_scan_rows <<<NCHUNKS, 256>>>(p_nt, ROWS);
    k_scan_tiles<<<1, 1024>>>(p_nt, NCHUNKS, out, N);
    k_scatter   <<<NBLOCKS, 256>>>(pos, cov, opac, p_nt, N, ROWS, out);
}

// round 3
// speedup vs baseline: 1.0037x; 1.0037x over previous
#include <cuda_runtime.h>
#include <cstdint>

// ---------------- configuration ----------------
#define TSTRIDE     1024        // padded tile stride in hist matrices (supports num_tile up to 32)
#define MAX_ROWS    8192        // supports N up to 4M at 512 pts/row
#define MAX_CHUNKS  256
#define PPW         512         // points per warp (one hist "row")
#define WPB         8           // warps per block
#define PPB         (PPW*WPB)   // 4096 points per block
#define CHUNK       64          // rows per scan chunk

// ---------------- static scratch (no runtime allocation) ----------------
__device__ int g_hist[MAX_ROWS * TSTRIDE];     // per-row tile histograms -> exclusive prefixes
__device__ int g_chunk[MAX_CHUNKS * TSTRIDE];  // per-chunk totals -> exclusive prefixes
__device__ int g_offsets[TSTRIDE];             // global tile offsets

// ---------------- helpers ----------------
__device__ __forceinline__ int tile_of(float v, float ts, int nt) {
    int t = (int)floorf(v / ts);
    t = t < 0 ? 0 : t;
    t = t > nt - 1 ? nt - 1 : t;
    return t;
}

// ---------------- pass 1: per-warp-row histogram ----------------
__global__ void k_hist(const float2* __restrict__ pos, const int* __restrict__ p_nt,
                       int N, int ROWS) {
    __shared__ int sh[WPB * TSTRIDE];   // 32 KB
    const int nt  = *p_nt;
    const int nt2 = nt * nt;
    const float ts = 1024.0f / (float)nt;

    const int w    = threadIdx.x >> 5;
    const int lane = threadIdx.x & 31;
    const int row  = blockIdx.x * WPB + w;

    // zero only this warp's columns
    for (int t = lane; t < nt2; t += 32) sh[w * TSTRIDE + t] = 0;
    __syncwarp();

    if (row >= ROWS) return;

    const int base = row * PPW;
#pragma unroll 4
    for (int i = 0; i < PPW / 32; i++) {
        int idx = base + i * 32 + lane;
        if (idx < N) {
            float2 p = pos[idx];
            int tx = tile_of(p.x, ts, nt);
            int ty = tile_of(p.y, ts, nt);
            atomicAdd(&sh[w * TSTRIDE + ty * nt + tx], 1);
        }
    }
    __syncwarp();
    for (int t = lane; t < nt2; t += 32)
        g_hist[(size_t)row * TSTRIDE + t] = sh[w * TSTRIDE + t];
}

// ---------------- pass 2a: per-tile scan over rows within each chunk ----------------
__global__ void k_scan_rows(const int* __restrict__ p_nt, int ROWS) {
    const int nt  = *p_nt;
    const int nt2 = nt * nt;
    const int c  = blockIdx.x;
    const int r0 = c * CHUNK;
    const int r1 = min(r0 + CHUNK, ROWS);

    for (int t = threadIdx.x; t < nt2; t += blockDim.x) {
        int run = 0;
        for (int r = r0; r < r1; r++) {
            int v = g_hist[(size_t)r * TSTRIDE + t];
            g_hist[(size_t)r * TSTRIDE + t] = run;
            run += v;
        }
        g_chunk[(size_t)c * TSTRIDE + t] = run;
    }
}

// ---------------- pass 2b: scan chunks per tile, then scan over tiles ----------------
__global__ void k_scan_tiles(const int* __restrict__ p_nt, int NCHUNKS,
                             float* __restrict__ out, int N) {
    __shared__ int s[1024];
    const int nt  = *p_nt;
    const int nt2 = nt * nt;
    const int t = threadIdx.x;

    int total = 0;
    if (t < nt2) {
        int run = 0;
        for (int c = 0; c < NCHUNKS; c++) {
            int v = g_chunk[(size_t)c * TSTRIDE + t];
            g_chunk[(size_t)c * TSTRIDE + t] = run;
            run += v;
        }
        total = run;
    }
    s[t] = total;
    __syncthreads();

    // Kogge-Stone inclusive scan over 1024 slots
    for (int off = 1; off < 1024; off <<= 1) {
        int v = (t >= off) ? s[t - off] : 0;
        __syncthreads();
        s[t] += v;
        __syncthreads();
    }
    int excl = s[t] - total;   // exclusive prefix

    if (t < nt2) {
        g_offsets[t] = excl;
        size_t feat_sz = (size_t)7 * (size_t)N;
        out[feat_sz + t]        = (float)total;  // tile_counts
        out[feat_sz + nt2 + t]  = (float)excl;   // tile_offsets
    }
}

// ---------------- pass 3: compute feat, stable rank, scatter ----------------
__global__ void k_scatter(const float2* __restrict__ pos,
                          const float4* __restrict__ cov,
                          const float*  __restrict__ opac,
                          const int*    __restrict__ p_nt,
                          int N, int ROWS,
                          float* __restrict__ out) {
    __shared__ int sb[WPB * TSTRIDE];   // 32 KB, per-warp base counters
    const int nt  = *p_nt;
    const int nt2 = nt * nt;
    const float ts = 1024.0f / (float)nt;

    const int w    = threadIdx.x >> 5;
    const int lane = threadIdx.x & 31;
    const int row  = blockIdx.x * WPB + w;

    float* __restrict__ out_feat  = out;
    float* __restrict__ out_order = out + (size_t)7 * (size_t)N + 2 * (size_t)nt2;

    if (row >= ROWS) return;

    // preload per-warp base: global tile offset + chunk prefix + row prefix
    const int chunk = row / CHUNK;
    for (int t = lane; t < nt2; t += 32)
        sb[w * TSTRIDE + t] = g_offsets[t]
                            + g_chunk[(size_t)chunk * TSTRIDE + t]
                            + g_hist[(size_t)row * TSTRIDE + t];
    __syncwarp();

    const int base = row * PPW;
    const unsigned lt_mask = (1u << lane) - 1u;

    for (int i = 0; i < PPW / 32; i++) {
        int idx = base + i * 32 + lane;
        bool valid = idx < N;

        float2 p = make_float2(0.f, 0.f);
        float ca = 0.f, cb = 0.f, cc = 0.f, rad = 0.f, op = 0.f;
        int key = 0x7FFFFFFF;   // sentinel for invalid lanes (never collides with a tile id)

        if (valid) {
            p = pos[idx];
            float4 cv = cov[idx];
            op = opac[idx];
            float a = cv.x, b = cv.y, c = cv.z, d = cv.w;
            float tr  = a + d;
            float det = a * d - b * c;
            float t1  = 0.5f * tr;
            float t2  = 0.5f * sqrtf(fmaxf(tr * tr - 4.0f * det, 0.0f));
            rad = fmaxf(t1 - t2, t1 + t2);
            float inv_det = 1.0f / det;
            ca =  d * inv_det;
            cb = -b * inv_det;
            cc =  a * inv_det;
            int tx = tile_of(p.x, ts, nt);
            int ty = tile_of(p.y, ts, nt);
            key = ty * nt + tx;
        }

        // stable rank within warp: groups of equal key in lane order
        unsigned m  = __match_any_sync(0xFFFFFFFFu, key);
        int leader  = __ffs(m) - 1;
        int cnt     = __popc(m);
        int rank_lt = __popc(m & lt_mask);

        int b0 = 0;
        if (lane == leader && valid) {
            b0 = sb[w * TSTRIDE + key];          // single writer per address: no atomic needed
            sb[w * TSTRIDE + key] = b0 + cnt;
        }
        b0 = __shfl_sync(0xFFFFFFFFu, b0, leader);

        if (valid) {
            size_t r = (size_t)(b0 + rank_lt);
            float* f = out_feat + r * 7;
            f[0] = p.x; f[1] = p.y;
            f[2] = ca;  f[3] = cb; f[4] = cc;
            f[5] = op;  f[6] = rad;
            out_order[r] = (float)idx;
        }
    }
}

// ---------------- launch ----------------
extern "C" void kernel_launch(void* const* d_in, const int* in_sizes, int n_in,
                              void* d_out, int out_size) {
    const float2* pos  = (const float2*)d_in[0];
    const float4* cov  = (const float4*)d_in[1];
    const float*  opac = (const float*) d_in[2];
    const int*    p_nt = (const int*)   d_in[3];
    float* out = (float*)d_out;

    const int N       = in_sizes[0] / 2;
    const int ROWS    = (N + PPW - 1) / PPW;
    const int NBLOCKS = (ROWS + WPB - 1) / WPB;
    const int NCHUNKS = (ROWS + CHUNK - 1) / CHUNK;

    k_hist      <<<NBLOCKS, 256>>>(pos, p_nt, N, ROWS);
    k_scan_rows <<<NCHUNKS, 256>>>(p_nt, ROWS);
    k_scan_tiles<<<1, 1024>>>(p_nt, NCHUNKS, out, N);
    k_scatter   <<<NBLOCKS, 256>>>(pos, cov, opac, p_nt, N, ROWS, out);
}

// round 4
// speedup vs baseline: 1.5293x; 1.5236x over previous
#include <cuda_runtime.h>
#include <cstdint>

// ---------------- configuration ----------------
#define TSTRIDE     1024        // padded tile stride in hist matrices (num_tile up to 32)
#define MAX_ROWS    8192        // supports N up to 4M at 512 pts/row
#define MAX_CHUNKS  256
#define PPW         512         // points per warp (one hist "row")
#define WPB         8           // warps per block
#define CHUNK       64          // rows per scan chunk
#define GTHREADS    256         // gather block size

// ---------------- static scratch (no runtime allocation) ----------------
__device__ int            g_hist [MAX_ROWS * TSTRIDE];   // per-row hist -> exclusive row prefixes
__device__ int            g_chunk[MAX_CHUNKS * TSTRIDE]; // per-chunk totals -> exclusive prefixes
__device__ int            g_offsets[TSTRIDE];            // global tile offsets
__device__ unsigned short g_keys [MAX_ROWS * PPW];       // per-point tile id (u16)
__device__ int            g_perm [MAX_ROWS * PPW];       // perm[r] = source index

// ---------------- helpers ----------------
__device__ __forceinline__ int tile_of(float v, float ts, int nt) {
    int t = (int)floorf(v / ts);
    t = t < 0 ? 0 : t;
    t = t > nt - 1 ? nt - 1 : t;
    return t;
}

// ---------------- pass 1: per-warp-row histogram + key store ----------------
__global__ void k_hist(const float2* __restrict__ pos, const int* __restrict__ p_nt,
                       int N, int ROWS) {
    __shared__ int sh[WPB * TSTRIDE];   // 32 KB
    const int nt  = *p_nt;
    const int nt2 = nt * nt;
    const float ts = 1024.0f / (float)nt;

    const int w    = threadIdx.x >> 5;
    const int lane = threadIdx.x & 31;
    const int row  = blockIdx.x * WPB + w;

    for (int t = lane; t < nt2; t += 32) sh[w * TSTRIDE + t] = 0;
    __syncwarp();

    if (row >= ROWS) return;

    const int base = row * PPW;
#pragma unroll 4
    for (int i = 0; i < PPW / 32; i++) {
        int idx = base + i * 32 + lane;
        if (idx < N) {
            float2 p = pos[idx];
            int tx = tile_of(p.x, ts, nt);
            int ty = tile_of(p.y, ts, nt);
            int key = ty * nt + tx;
            g_keys[idx] = (unsigned short)key;
            atomicAdd(&sh[w * TSTRIDE + key], 1);
        }
    }
    __syncwarp();
    for (int t = lane; t < nt2; t += 32)
        g_hist[(size_t)row * TSTRIDE + t] = sh[w * TSTRIDE + t];
}

// ---------------- pass 2a: per-tile scan over rows within each chunk ----------------
__global__ void k_scan_rows(const int* __restrict__ p_nt, int ROWS) {
    const int nt  = *p_nt;
    const int nt2 = nt * nt;
    const int c  = blockIdx.x;
    const int r0 = c * CHUNK;
    const int r1 = min(r0 + CHUNK, ROWS);

    for (int t = threadIdx.x; t < nt2; t += blockDim.x) {
        int run = 0;
        for (int r = r0; r < r1; r += 8) {
            int m = min(8, r1 - r);
            int v[8];
#pragma unroll
            for (int j = 0; j < 8; j++)
                if (j < m) v[j] = g_hist[(size_t)(r + j) * TSTRIDE + t];
#pragma unroll
            for (int j = 0; j < 8; j++)
                if (j < m) {
                    g_hist[(size_t)(r + j) * TSTRIDE + t] = run;
                    run += v[j];
                }
        }
        g_chunk[(size_t)c * TSTRIDE + t] = run;
    }
}

// ---------------- pass 2b: scan chunks per tile, then scan over tiles ----------------
__global__ void k_scan_tiles(const int* __restrict__ p_nt, int NCHUNKS,
                             float* __restrict__ out, int N) {
    __shared__ int s[1024];
    const int nt  = *p_nt;
    const int nt2 = nt * nt;
    const int t = threadIdx.x;

    int total = 0;
    if (t < nt2) {
        int run = 0;
        for (int c = 0; c < NCHUNKS; c += 8) {
            int m = min(8, NCHUNKS - c);
            int v[8];
#pragma unroll
            for (int j = 0; j < 8; j++)
                if (j < m) v[j] = g_chunk[(size_t)(c + j) * TSTRIDE + t];
#pragma unroll
            for (int j = 0; j < 8; j++)
                if (j < m) {
                    g_chunk[(size_t)(c + j) * TSTRIDE + t] = run;
                    run += v[j];
                }
        }
        total = run;
    }
    s[t] = total;
    __syncthreads();

    for (int off = 1; off < 1024; off <<= 1) {
        int v = (t >= off) ? s[t - off] : 0;
        __syncthreads();
        s[t] += v;
        __syncthreads();
    }
    int excl = s[t] - total;

    if (t < nt2) {
        g_offsets[t] = excl;
        size_t feat_sz = (size_t)7 * (size_t)N;
        out[feat_sz + t]       = (float)total;  // tile_counts
        out[feat_sz + nt2 + t] = (float)excl;   // tile_offsets
    }
}

// ---------------- pass 3a: stable rank, scatter permutation only (4B/pt) ----------------
__global__ void k_rank(const int* __restrict__ p_nt, int N, int ROWS) {
    __shared__ int sb[WPB * TSTRIDE];   // 32 KB, per-warp base counters
    const int nt  = *p_nt;
    const int nt2 = nt * nt;

    const int w    = threadIdx.x >> 5;
    const int lane = threadIdx.x & 31;
    const int row  = blockIdx.x * WPB + w;

    if (row >= ROWS) return;

    const int chunk = row / CHUNK;
    for (int t = lane; t < nt2; t += 32)
        sb[w * TSTRIDE + t] = g_offsets[t]
                            + g_chunk[(size_t)chunk * TSTRIDE + t]
                            + g_hist[(size_t)row * TSTRIDE + t];
    __syncwarp();

    const int base = row * PPW;
    const unsigned lt_mask = (1u << lane) - 1u;

#pragma unroll 2
    for (int i = 0; i < PPW / 32; i++) {
        int idx = base + i * 32 + lane;
        bool valid = idx < N;
        int key = valid ? (int)g_keys[idx] : 0x7FFFFFFF;

        unsigned m  = __match_any_sync(0xFFFFFFFFu, key);
        int leader  = __ffs(m) - 1;
        int cnt     = __popc(m);
        int rank_lt = __popc(m & lt_mask);

        int b0 = 0;
        if (lane == leader && valid) {
            b0 = sb[w * TSTRIDE + key];
            sb[w * TSTRIDE + key] = b0 + cnt;
        }
        b0 = __shfl_sync(0xFFFFFFFFu, b0, leader);

        if (valid) g_perm[b0 + rank_lt] = idx;
    }
}

// ---------------- pass 3b: gather + compute + coalesced wide stores ----------------
__global__ void k_gather(const float2* __restrict__ pos,
                         const float4* __restrict__ cov,
                         const float*  __restrict__ opac,
                         const int*    __restrict__ p_nt,
                         int N,
                         float* __restrict__ out) {
    __shared__ float s[GTHREADS * 7];   // 7 KB staging; stride 7 -> conflict-free
    const int nt  = *p_nt;
    const int nt2 = nt * nt;

    const int tid = threadIdx.x;
    const int r0  = blockIdx.x * GTHREADS;
    const int r   = r0 + tid;

    float* __restrict__ out_order = out + (size_t)7 * (size_t)N + 2 * (size_t)nt2;

    if (r < N) {
        int idx = g_perm[r];
        float2 p  = __ldg(&pos[idx]);
        float4 cv = __ldg(&cov[idx]);
        float  op = __ldg(&opac[idx]);

        float a = cv.x, b = cv.y, c = cv.z, d = cv.w;
        float tr  = a + d;
        float det = a * d - b * c;
        float t1  = 0.5f * tr;
        float t2  = 0.5f * sqrtf(fmaxf(tr * tr - 4.0f * det, 0.0f));
        float rad = fmaxf(t1 - t2, t1 + t2);
        float inv_det = 1.0f / det;

        float* sf = s + tid * 7;
        sf[0] = p.x;  sf[1] = p.y;
        sf[2] =  d * inv_det;
        sf[3] = -b * inv_det;
        sf[4] =  a * inv_det;
        sf[5] = op;   sf[6] = rad;

        out_order[r] = (float)idx;
    }
    __syncthreads();

    // cooperative coalesced copy of the staged feat tile
    int count = min(GTHREADS, N - r0);
    if (count == GTHREADS) {
        // full tile: 1792 floats = 448 float4, base aligned (r0 multiple of 256)
        float4* dst = (float4*)(out + (size_t)r0 * 7);
        const float4* src = (const float4*)s;
#pragma unroll
        for (int i = 0; i < (GTHREADS * 7) / (4 * GTHREADS) + 1; i++) {
            int j = tid + i * GTHREADS;
            if (j < (GTHREADS * 7) / 4) dst[j] = src[j];
        }
    } else if (count > 0) {
        float* dst = out + (size_t)r0 * 7;
        int nf = count * 7;
        for (int j = tid; j < nf; j += GTHREADS) dst[j] = s[j];
    }
}

// ---------------- launch ----------------
extern "C" void kernel_launch(void* const* d_in, const int* in_sizes, int n_in,
                              void* d_out, int out_size) {
    const float2* pos  = (const float2*)d_in[0];
    const float4* cov  = (const float4*)d_in[1];
    const float*  opac = (const float*) d_in[2];
    const int*    p_nt = (const int*)   d_in[3];
    float* out = (float*)d_out;

    const int N       = in_sizes[0] / 2;
    const int ROWS    = (N + PPW - 1) / PPW;
    const int NBLOCKS = (ROWS + WPB - 1) / WPB;
    const int NCHUNKS = (ROWS + CHUNK - 1) / CHUNK;
    const int GBLOCKS = (N + GTHREADS - 1) / GTHREADS;

    k_hist      <<<NBLOCKS, 256>>>(pos, p_nt, N, ROWS);
    k_scan_rows <<<NCHUNKS, 256>>>(p_nt, ROWS);
    k_scan_tiles<<<1, 1024>>>(p_nt, NCHUNKS, out, N);
    k_rank      <<<NBLOCKS, 256>>>(p_nt, N, ROWS);
    k_gather    <<<GBLOCKS, GTHREADS>>>(pos, cov, opac, p_nt, N, out);
}